// round 2
// baseline (speedup 1.0000x reference)
#include <cuda_runtime.h>
#include <cuda_bf16.h>
#include <cstdint>

// Thole dipole-dipole tensor per edge.
// au3 = 0.39 * d^3 / sqrt(p_i p_j)   (angstrom-unit conversions cancel)
// l3  = 1 - e^-au3 ; l5 = 1 - (1+au3) e^-au3
// T   = BOHR^3 * ( 3 l5 * v v^T / d^5  -  l3 * I / d^3 )

#define BOHR 0.52917721067f
#define A_MUTUAL 0.39f

static constexpr int TPB = 256;
static constexpr int EPB = TPB * 2;   // edges per block (2 per thread, strided)

__global__ __launch_bounds__(TPB)
void thole_kernel(const int* __restrict__ edge_src,
                  const int* __restrict__ edge_dst,
                  const float* __restrict__ distances,
                  const float* __restrict__ vec,
                  const float* __restrict__ pol,
                  float* __restrict__ out,
                  int E)
{
    __shared__ __align__(16) float s[EPB * 9];

    const int tid = threadIdx.x;
    const long long blockStart = (long long)blockIdx.x * EPB;
    const float BOHR3 = BOHR * BOHR * BOHR;

    const long long e0 = blockStart + tid;
    const long long e1 = blockStart + TPB + tid;
    const bool v0 = e0 < E;
    const bool v1 = e1 < E;

    // ---- issue all independent memory ops first (MLP) ----
    int   i0s = 0, i0d = 0, i1s = 0, i1d = 0;
    float d0 = 1.f, d1 = 1.f;
    float vx0 = 0.f, vy0 = 0.f, vz0 = 0.f, vx1 = 0.f, vy1 = 0.f, vz1 = 0.f;

    if (v0) {
        i0s = __ldcs(edge_src + e0);
        i0d = __ldcs(edge_dst + e0);
        d0  = __ldcs(distances + e0);
        vx0 = __ldcs(vec + 3 * e0 + 0);
        vy0 = __ldcs(vec + 3 * e0 + 1);
        vz0 = __ldcs(vec + 3 * e0 + 2);
    }
    if (v1) {
        i1s = __ldcs(edge_src + e1);
        i1d = __ldcs(edge_dst + e1);
        d1  = __ldcs(distances + e1);
        vx1 = __ldcs(vec + 3 * e1 + 0);
        vy1 = __ldcs(vec + 3 * e1 + 1);
        vz1 = __ldcs(vec + 3 * e1 + 2);
    }

    // gathers (default caching: keep pol table resident in L1)
    float p0s = 1.f, p0d = 1.f, p1s = 1.f, p1d = 1.f;
    if (v0) { p0s = __ldg(pol + i0s); p0d = __ldg(pol + i0d); }
    if (v1) { p1s = __ldg(pol + i1s); p1d = __ldg(pol + i1d); }

    // ---- compute + stage edge 0 ----
    {
        const float d2 = d0 * d0, d3 = d2 * d0;
        const float au3 = A_MUTUAL * d3 * rsqrtf(p0s * p0d);
        const float ex  = __expf(-au3);
        const float l3  = 1.0f - ex;
        const float l5  = 1.0f - (1.0f + au3) * ex;
        const float inv_d3 = __frcp_rn(d3);
        const float inv_d5 = inv_d3 * __frcp_rn(d2);
        const float c5 = 3.0f * l5 * inv_d5 * BOHR3;
        const float c3 = l3 * inv_d3 * BOHR3;
        float* t = &s[tid * 9];
        const float c5x = c5 * vx0, c5y = c5 * vy0, c5z = c5 * vz0;
        t[0] = c5x * vx0 - c3;
        t[1] = c5x * vy0;
        t[2] = c5x * vz0;
        t[3] = c5y * vx0;
        t[4] = c5y * vy0 - c3;
        t[5] = c5y * vz0;
        t[6] = c5z * vx0;
        t[7] = c5z * vy0;
        t[8] = c5z * vz0 - c3;
    }
    // ---- compute + stage edge 1 ----
    {
        const float d2 = d1 * d1, d3 = d2 * d1;
        const float au3 = A_MUTUAL * d3 * rsqrtf(p1s * p1d);
        const float ex  = __expf(-au3);
        const float l3  = 1.0f - ex;
        const float l5  = 1.0f - (1.0f + au3) * ex;
        const float inv_d3 = __frcp_rn(d3);
        const float inv_d5 = inv_d3 * __frcp_rn(d2);
        const float c5 = 3.0f * l5 * inv_d5 * BOHR3;
        const float c3 = l3 * inv_d3 * BOHR3;
        float* t = &s[(TPB + tid) * 9];
        const float c5x = c5 * vx1, c5y = c5 * vy1, c5z = c5 * vz1;
        t[0] = c5x * vx1 - c3;
        t[1] = c5x * vy1;
        t[2] = c5x * vz1;
        t[3] = c5y * vx1;
        t[4] = c5y * vy1;   // off-diag
        t[4] = c5y * vy1 - c3;
        t[5] = c5y * vz1;
        t[6] = c5z * vx1;
        t[7] = c5z * vy1;
        t[8] = c5z * vz1 - c3;
    }
    __syncthreads();

    // ---- flush staging to global, coalesced, streaming (evict-first) ----
    const long long remaining = (long long)E - blockStart;
    const int nEdges = remaining >= EPB ? EPB : (int)remaining;
    const int nFloats = nEdges * 9;
    float* outBase = out + blockStart * 9;

    if (nFloats == EPB * 9) {
        const float4* s4 = reinterpret_cast<const float4*>(s);
        float4* o4 = reinterpret_cast<float4*>(outBase);
        #pragma unroll
        for (int i = tid; i < EPB * 9 / 4; i += TPB)
            __stcs(o4 + i, s4[i]);
    } else {
        for (int i = tid; i < nFloats; i += TPB)
            __stcs(outBase + i, s[i]);
    }
}

extern "C" void kernel_launch(void* const* d_in, const int* in_sizes, int n_in,
                              void* d_out, int out_size)
{
    const int*   edge_src = (const int*)  d_in[1];
    const int*   edge_dst = (const int*)  d_in[2];
    const float* dist     = (const float*)d_in[3];
    const float* vec      = (const float*)d_in[4];
    const float* pol      = (const float*)d_in[5];
    float* out = (float*)d_out;

    const int E = in_sizes[1];
    const int blocks = (E + EPB - 1) / EPB;
    thole_kernel<<<blocks, TPB>>>(edge_src, edge_dst, dist, vec, pol, out, E);
}